// round 1
// baseline (speedup 1.0000x reference)
#include <cuda_runtime.h>
#include <math.h>

#define HW    128
#define CIN   256
#define DLOI  128
#define NB    8
#define NL    2048
#define NLINES (NB*NL)
#define PLANES 64
#define BN_EPS 1e-5f

// Scratch: fc1 output in NHWC layout [b][i][j][o]  (64 MB)
__device__ float g_x[(size_t)NB * HW * HW * DLOI];
// Scratch: sampled+maxpooled features [n][c][t]    (64 MB)
__device__ float g_xp[(size_t)NLINES * DLOI * 8];

// ---------------------------------------------------------------------------
// K1: fc1 1x1 conv as SGEMM.  x[b, i, j, o] = sum_c W[o,c] * F[b,c,i,j] + bias
// Block: 64 pixels x 128 outputs, 256 threads, micro-tile 4pix x 8o.
// ---------------------------------------------------------------------------
__global__ __launch_bounds__(256) void k_fc1(const float* __restrict__ feat,
                                             const float* __restrict__ w,
                                             const float* __restrict__ bias) {
    __shared__ float sa[32][64];
    __shared__ float sw[32][132];   // padded rows, float4-aligned
    const int b = blockIdx.y;
    const int pixbase = blockIdx.x * 64;
    const int tid = threadIdx.x;
    const int og = tid & 15;    // o-group: o0 = og*8
    const int pg = tid >> 4;    // pix-group: pix0 = pg*4

    float acc[4][8];
#pragma unroll
    for (int i = 0; i < 4; i++)
#pragma unroll
        for (int j = 0; j < 8; j++) acc[i][j] = 0.f;

    const float* fb = feat + (size_t)b * CIN * HW * HW;

    for (int kc = 0; kc < CIN; kc += 32) {
#pragma unroll
        for (int r = 0; r < 8; r++) {
            int idx = tid + r * 256;
            sa[idx >> 6][idx & 63] =
                fb[(size_t)(kc + (idx >> 6)) * (HW * HW) + pixbase + (idx & 63)];
        }
#pragma unroll
        for (int r = 0; r < 16; r++) {
            int idx = tid + r * 256;
            int o = idx >> 5, k = idx & 31;
            sw[k][o] = w[o * CIN + kc + k];
        }
        __syncthreads();
#pragma unroll
        for (int k = 0; k < 32; k++) {
            float4 av = *(const float4*)&sa[k][pg * 4];
            float4 w0 = *(const float4*)&sw[k][og * 8];
            float4 w1 = *(const float4*)&sw[k][og * 8 + 4];
            float a[4]  = {av.x, av.y, av.z, av.w};
            float wv[8] = {w0.x, w0.y, w0.z, w0.w, w1.x, w1.y, w1.z, w1.w};
#pragma unroll
            for (int i = 0; i < 4; i++)
#pragma unroll
                for (int j = 0; j < 8; j++) acc[i][j] += a[i] * wv[j];
        }
        __syncthreads();
    }

    float bv[8];
#pragma unroll
    for (int j = 0; j < 8; j++) bv[j] = bias[og * 8 + j];
#pragma unroll
    for (int i = 0; i < 4; i++) {
        size_t pix = (size_t)pixbase + pg * 4 + i;
        float* dst = &g_x[((size_t)b * (HW * HW) + pix) * DLOI + og * 8];
        float4 o0 = make_float4(acc[i][0] + bv[0], acc[i][1] + bv[1],
                                acc[i][2] + bv[2], acc[i][3] + bv[3]);
        float4 o1 = make_float4(acc[i][4] + bv[4], acc[i][5] + bv[5],
                                acc[i][6] + bv[6], acc[i][7] + bv[7]);
        *(float4*)dst = o0;
        *(float4*)(dst + 4) = o1;
    }
}

// ---------------------------------------------------------------------------
// K2: bilinear sampling of 32 points per line + maxpool(4) -> g_xp[n][c][t]
// One block per line, 128 threads (thread = channel).
// ---------------------------------------------------------------------------
__global__ __launch_bounds__(128) void k_sample(const float* __restrict__ lines) {
    __shared__ float swt[4][32];
    __shared__ int   soff[4][32];
    const int n = blockIdx.x;
    const int b = n >> 11;
    const int c = threadIdx.x;
    const float* lp = lines + (size_t)n * 4;

    if (c < 32) {
        int p = c;
        float lam = (float)p * (1.0f / 31.0f);
        float l0x = lp[0], l0y = lp[1], l1x = lp[2], l1y = lp[3];
        float px = l0x * lam + l1x * (1.f - lam) - 0.5f;
        float py = l0y * lam + l1y * (1.f - lam) - 0.5f;
        float px0 = fminf(fmaxf(floorf(px), 0.f), 127.f);
        float py0 = fminf(fmaxf(floorf(py), 0.f), 127.f);
        float px1 = fminf(px0 + 1.f, 127.f);
        float py1 = fminf(py0 + 1.f, 127.f);
        int ix0 = (int)px0, iy0 = (int)py0, ix1 = (int)px1, iy1 = (int)py1;
        swt[0][p] = (px1 - px) * (py1 - py);
        swt[1][p] = (px - px0) * (py1 - py);
        swt[2][p] = (px1 - px) * (py - py0);
        swt[3][p] = (px - px0) * (py - py0);
        soff[0][p] = (ix0 * HW + iy0) * DLOI;
        soff[1][p] = (ix1 * HW + iy0) * DLOI;
        soff[2][p] = (ix0 * HW + iy1) * DLOI;
        soff[3][p] = (ix1 * HW + iy1) * DLOI;
    }
    __syncthreads();

    const float* xb = g_x + (size_t)b * (HW * HW) * DLOI + c;
    float xpv[8];
#pragma unroll
    for (int t = 0; t < 8; t++) {
        float m = -3.4e38f;
#pragma unroll
        for (int j = 0; j < 4; j++) {
            int p = t * 4 + j;
            float s = xb[soff[0][p]] * swt[0][p]
                    + xb[soff[1][p]] * swt[1][p]
                    + xb[soff[2][p]] * swt[2][p]
                    + xb[soff[3][p]] * swt[3][p];
            m = fmaxf(m, s);
        }
        xpv[t] = m;
    }
    float* dst = g_xp + (size_t)n * (DLOI * 8) + c * 8;
    *(float4*)dst       = make_float4(xpv[0], xpv[1], xpv[2], xpv[3]);
    *(float4*)(dst + 4) = make_float4(xpv[4], xpv[5], xpv[6], xpv[7]);
}

// ---------------------------------------------------------------------------
// K3: Bottleneck1D + residual + fc2.  8 lines per block, 256 threads.
// All weights staged in shared memory in lane-contiguous (transposed) layouts.
// ---------------------------------------------------------------------------
// smem layout (float offsets)
#define OF_W1    0        // 8192  w1s[c*64 + p]
#define OF_W2    8192     // 12288 w2s[(i*3+dt)*64 + q]
#define OF_W3    20480    // 8192  w3s[q*128 + o]
#define OF_XP    28672    // 8192  xp_s[ln][c][t]
#define OF_A     36864    // 8192  a_s = relu(bn1(xp))
#define OF_B     45056    // 5120  b_s[ln][p][10] (zero-padded t)
#define OF_C     50176    // 4096  c_s[ln][q][8]
#define OF_CONST 54272    // 1792  (see offsets below)
#define OF_RED   56064    // 1024
#define K3_SMEM_FLOATS 57088
#define K3_SMEM_BYTES  (K3_SMEM_FLOATS * 4)
// const sub-offsets: c1b@0, s2@64, o2@128, c2b@192, s3@256, o3@320,
//                    c3b@384, s1@512, o1@640, fc2w@768

__global__ void __launch_bounds__(256, 1) k_bottleneck(
    const float* __restrict__ bn1g, const float* __restrict__ bn1b,
    const float* __restrict__ bn1m, const float* __restrict__ bn1v,
    const float* __restrict__ c1w,  const float* __restrict__ c1b,
    const float* __restrict__ bn2g, const float* __restrict__ bn2b,
    const float* __restrict__ bn2m, const float* __restrict__ bn2v,
    const float* __restrict__ c2w,  const float* __restrict__ c2b,
    const float* __restrict__ bn3g, const float* __restrict__ bn3b,
    const float* __restrict__ bn3m, const float* __restrict__ bn3v,
    const float* __restrict__ c3w,  const float* __restrict__ c3b,
    const float* __restrict__ fc2w, const float* __restrict__ fc2b,
    float* __restrict__ out)
{
    extern __shared__ float sm[];
    const int tid = threadIdx.x;
    const int n0 = blockIdx.x * 8;

    // ---- stage weights (transposed for conflict-free reads) ----
#pragma unroll
    for (int r = 0; r < 32; r++) {
        int idx = tid + r * 256;                     // [p][c] -> [c][p]
        sm[OF_W1 + (idx & 127) * 64 + (idx >> 7)] = c1w[idx];
    }
#pragma unroll
    for (int r = 0; r < 48; r++) {
        int idx = tid + r * 256;                     // [q][i][dt] -> [(i*3+dt)][q]
        int q = idx / 192;
        int rem = idx - q * 192;
        sm[OF_W2 + rem * 64 + q] = c2w[idx];
    }
#pragma unroll
    for (int r = 0; r < 32; r++) {
        int idx = tid + r * 256;                     // [o][q] -> [q][o]
        sm[OF_W3 + (idx & 63) * 128 + (idx >> 6)] = c3w[idx];
    }
    // ---- stage consts ----
    if (tid < 64) {
        float s2 = bn2g[tid] * rsqrtf(bn2v[tid] + BN_EPS);
        sm[OF_CONST + 64 + tid]  = s2;
        sm[OF_CONST + 128 + tid] = bn2b[tid] - bn2m[tid] * s2;
        sm[OF_CONST + 0 + tid]   = c1b[tid];
        float s3 = bn3g[tid] * rsqrtf(bn3v[tid] + BN_EPS);
        sm[OF_CONST + 256 + tid] = s3;
        sm[OF_CONST + 320 + tid] = bn3b[tid] - bn3m[tid] * s3;
        sm[OF_CONST + 192 + tid] = c2b[tid];
    }
    if (tid < 128) {
        sm[OF_CONST + 384 + tid] = c3b[tid];
        float s1 = bn1g[tid] * rsqrtf(bn1v[tid] + BN_EPS);
        sm[OF_CONST + 512 + tid] = s1;
        sm[OF_CONST + 640 + tid] = bn1b[tid] - bn1m[tid] * s1;
    }
#pragma unroll
    for (int r = 0; r < 4; r++)
        sm[OF_CONST + 768 + tid + r * 256] = fc2w[tid + r * 256];

    // ---- stage xp (8 lines) ----
    {
        const float4* src = (const float4*)(g_xp + (size_t)n0 * (DLOI * 8));
        float4* dst = (float4*)(sm + OF_XP);
#pragma unroll
        for (int r = 0; r < 8; r++) dst[tid + r * 256] = src[tid + r * 256];
    }
    __syncthreads();

    // ---- a_s = relu(bn1(xp)) ----
#pragma unroll
    for (int r = 0; r < 32; r++) {
        int idx = tid + r * 256;            // [ln][c][t]
        int cch = (idx >> 3) & 127;
        float v = sm[OF_XP + idx] * sm[OF_CONST + 512 + cch] + sm[OF_CONST + 640 + cch];
        sm[OF_A + idx] = fmaxf(v, 0.f);
    }
    __syncthreads();

    // ---- conv1 (128->64) + bias + bn2 + relu -> b_s ----
    {
        int p = tid & 63, g = tid >> 6;          // lines {g, g+4}
        float acc[2][8];
#pragma unroll
        for (int a = 0; a < 2; a++)
#pragma unroll
            for (int t = 0; t < 8; t++) acc[a][t] = 0.f;
#pragma unroll 4
        for (int cc = 0; cc < 128; cc++) {
            float wv = sm[OF_W1 + cc * 64 + p];
            const float* A0 = sm + OF_A + ((g) * 128 + cc) * 8;
            const float* A1 = sm + OF_A + ((g + 4) * 128 + cc) * 8;
            float4 u0 = *(const float4*)A0, u1 = *(const float4*)(A0 + 4);
            float4 v0 = *(const float4*)A1, v1 = *(const float4*)(A1 + 4);
            acc[0][0] += wv * u0.x; acc[0][1] += wv * u0.y;
            acc[0][2] += wv * u0.z; acc[0][3] += wv * u0.w;
            acc[0][4] += wv * u1.x; acc[0][5] += wv * u1.y;
            acc[0][6] += wv * u1.z; acc[0][7] += wv * u1.w;
            acc[1][0] += wv * v0.x; acc[1][1] += wv * v0.y;
            acc[1][2] += wv * v0.z; acc[1][3] += wv * v0.w;
            acc[1][4] += wv * v1.x; acc[1][5] += wv * v1.y;
            acc[1][6] += wv * v1.z; acc[1][7] += wv * v1.w;
        }
        float s2 = sm[OF_CONST + 64 + p], o2 = sm[OF_CONST + 128 + p];
        float bb = sm[OF_CONST + p];
#pragma unroll
        for (int ln2 = 0; ln2 < 2; ln2++) {
            int ln = g + ln2 * 4;
            float* Brow = sm + OF_B + (ln * 64 + p) * 10;
            Brow[0] = 0.f; Brow[9] = 0.f;
#pragma unroll
            for (int t = 0; t < 8; t++) {
                float v = (acc[ln2][t] + bb) * s2 + o2;
                Brow[1 + t] = fmaxf(v, 0.f);
            }
        }
    }
    __syncthreads();

    // ---- conv2 (3-tap, 64->64) + bias + bn3 + relu -> c_s ----
    {
        int q = tid & 63, g = tid >> 6;          // lines {g, g+4}
        float acc[2][8];
#pragma unroll
        for (int a = 0; a < 2; a++)
#pragma unroll
            for (int t = 0; t < 8; t++) acc[a][t] = 0.f;
#pragma unroll 2
        for (int i = 0; i < 64; i++) {
            float w0  = sm[OF_W2 + (i * 3 + 0) * 64 + q];
            float w1v = sm[OF_W2 + (i * 3 + 1) * 64 + q];
            float w2v = sm[OF_W2 + (i * 3 + 2) * 64 + q];
#pragma unroll
            for (int ln2 = 0; ln2 < 2; ln2++) {
                int ln = g + ln2 * 4;
                const float* Brow = sm + OF_B + (ln * 64 + i) * 10;
                float in[10];
#pragma unroll
                for (int j = 0; j < 10; j++) in[j] = Brow[j];
#pragma unroll
                for (int t = 0; t < 8; t++)
                    acc[ln2][t] += w0 * in[t] + w1v * in[t + 1] + w2v * in[t + 2];
            }
        }
        float s3 = sm[OF_CONST + 256 + q], o3v = sm[OF_CONST + 320 + q];
        float bb = sm[OF_CONST + 192 + q];
#pragma unroll
        for (int ln2 = 0; ln2 < 2; ln2++) {
            int ln = g + ln2 * 4;
            float* Crow = sm + OF_C + (ln * 64 + q) * 8;
#pragma unroll
            for (int t = 0; t < 8; t++)
                Crow[t] = fmaxf((acc[ln2][t] + bb) * s3 + o3v, 0.f);
        }
    }
    __syncthreads();

    // ---- conv3 (64->128) + residual + relu + fc2 partial ----
    {
        int o = tid & 127, g = tid >> 7;         // lines {g, g+2, g+4, g+6}
        float acc[4][8];
#pragma unroll
        for (int a = 0; a < 4; a++)
#pragma unroll
            for (int t = 0; t < 8; t++) acc[a][t] = 0.f;
#pragma unroll 2
        for (int q = 0; q < 64; q++) {
            float wv = sm[OF_W3 + q * 128 + o];
#pragma unroll
            for (int k = 0; k < 4; k++) {
                const float* Crow = sm + OF_C + ((g + 2 * k) * 64 + q) * 8;
                float4 u0 = *(const float4*)Crow, u1 = *(const float4*)(Crow + 4);
                acc[k][0] += wv * u0.x; acc[k][1] += wv * u0.y;
                acc[k][2] += wv * u0.z; acc[k][3] += wv * u0.w;
                acc[k][4] += wv * u1.x; acc[k][5] += wv * u1.y;
                acc[k][6] += wv * u1.z; acc[k][7] += wv * u1.w;
            }
        }
        float bb = sm[OF_CONST + 384 + o];
        float fw[8];
#pragma unroll
        for (int t = 0; t < 8; t++) fw[t] = sm[OF_CONST + 768 + o * 8 + t];
#pragma unroll
        for (int k = 0; k < 4; k++) {
            int ln = g + 2 * k;
            const float* X = sm + OF_XP + (ln * 128 + o) * 8;
            float lsum = 0.f;
#pragma unroll
            for (int t = 0; t < 8; t++) {
                float v = fmaxf(X[t] + acc[k][t] + bb, 0.f);
                lsum += v * fw[t];
            }
            sm[OF_RED + ln * 128 + o] = lsum;
        }
    }
    __syncthreads();

    // ---- reduce 128 partials per line, write logits ----
    {
        int ln = tid >> 5, lane = tid & 31;
        float s = sm[OF_RED + ln * 128 + lane]
                + sm[OF_RED + ln * 128 + lane + 32]
                + sm[OF_RED + ln * 128 + lane + 64]
                + sm[OF_RED + ln * 128 + lane + 96];
#pragma unroll
        for (int off = 16; off > 0; off >>= 1)
            s += __shfl_xor_sync(0xffffffffu, s, off);
        if (lane == 0) out[n0 + ln] = s + fc2b[0];
    }
}

// ---------------------------------------------------------------------------
extern "C" void kernel_launch(void* const* d_in, const int* in_sizes, int n_in,
                              void* d_out, int out_size) {
    const float* feature = (const float*)d_in[0];
    const float* lines   = (const float*)d_in[1];
    const float* fc1_w   = (const float*)d_in[2];
    const float* fc1_b   = (const float*)d_in[3];
    const float* bn1g = (const float*)d_in[4];
    const float* bn1b = (const float*)d_in[5];
    const float* bn1m = (const float*)d_in[6];
    const float* bn1v = (const float*)d_in[7];
    const float* c1w  = (const float*)d_in[8];
    const float* c1b  = (const float*)d_in[9];
    const float* bn2g = (const float*)d_in[10];
    const float* bn2b = (const float*)d_in[11];
    const float* bn2m = (const float*)d_in[12];
    const float* bn2v = (const float*)d_in[13];
    const float* c2w  = (const float*)d_in[14];
    const float* c2b  = (const float*)d_in[15];
    const float* bn3g = (const float*)d_in[16];
    const float* bn3b = (const float*)d_in[17];
    const float* bn3m = (const float*)d_in[18];
    const float* bn3v = (const float*)d_in[19];
    const float* c3w  = (const float*)d_in[20];
    const float* c3b  = (const float*)d_in[21];
    const float* fc2w = (const float*)d_in[22];
    const float* fc2b = (const float*)d_in[23];
    float* out = (float*)d_out;

    cudaFuncSetAttribute(k_bottleneck,
                         cudaFuncAttributeMaxDynamicSharedMemorySize,
                         K3_SMEM_BYTES);

    dim3 g1(HW * HW / 64, NB);
    k_fc1<<<g1, 256>>>(feature, fc1_w, fc1_b);
    k_sample<<<NLINES, 128>>>(lines);
    k_bottleneck<<<NLINES / 8, 256, K3_SMEM_BYTES>>>(
        bn1g, bn1b, bn1m, bn1v, c1w, c1b,
        bn2g, bn2b, bn2m, bn2v, c2w, c2b,
        bn3g, bn3b, bn3m, bn3v, c3w, c3b,
        fc2w, fc2b, out);
}

// round 2
// speedup vs baseline: 1.1478x; 1.1478x over previous
#include <cuda_runtime.h>
#include <math.h>

#define HW    128
#define CIN   256
#define DLOI  128
#define NB    8
#define NL    2048
#define NLINES (NB*NL)
#define PLANES 64
#define BN_EPS 1e-5f

// Scratch: fc1 output in NHWC layout [b][i][j][o]  (64 MB)
__device__ float g_x[(size_t)NB * HW * HW * DLOI];
// Scratch: sampled+maxpooled features [n][c][t]    (64 MB)
__device__ float g_xp[(size_t)NLINES * DLOI * 8];

// ---- packed f32x2 helpers (sm_103a dual-fp32 pipe) ----
typedef unsigned long long u64;

__device__ __forceinline__ u64 dup2(float x) {
    u64 r; asm("mov.b64 %0, {%1, %1};" : "=l"(r) : "f"(x)); return r;
}
__device__ __forceinline__ float2 unpack2(u64 v) {
    float2 f; asm("mov.b64 {%0, %1}, %2;" : "=f"(f.x), "=f"(f.y) : "l"(v)); return f;
}
__device__ __forceinline__ void fma2(u64& d, u64 a, u64 b) {
    asm("fma.rn.f32x2 %0, %1, %2, %0;" : "+l"(d) : "l"(a), "l"(b));
}

// ---------------------------------------------------------------------------
// K1: fc1 1x1 conv as SGEMM with f32x2.  x[b,pix,o] = sum_c W[o,c]*F[b,c,pix]+b
// Block tile 128 pix x 128 out, 256 threads, thread tile 8pix x 8out,
// pixel pairs packed (loaded pre-packed as ulonglong2 from smem).
// ---------------------------------------------------------------------------
__global__ __launch_bounds__(256, 2) void k_fc1(const float* __restrict__ feat,
                                                const float* __restrict__ w,
                                                const float* __restrict__ bias) {
    __shared__ float sa[16][128];   // [k][pix]
    __shared__ float sw[16][132];   // [k][o], padded (132*4 % 16 == 0)
    const int b = blockIdx.y;
    const int pixbase = blockIdx.x * 128;
    const int tid = threadIdx.x;
    const int tx = tid & 15;    // out group: o0 = tx*8
    const int ty = tid >> 4;    // pix group: p0 = ty*8

    u64 acc[4][8];              // [pix-pair][out]
#pragma unroll
    for (int i = 0; i < 4; i++)
#pragma unroll
        for (int j = 0; j < 8; j++) acc[i][j] = 0ULL;

    const float* fb = feat + (size_t)b * CIN * HW * HW + pixbase;

    for (int kc = 0; kc < CIN; kc += 16) {
#pragma unroll
        for (int r = 0; r < 8; r++) {
            int idx = tid + r * 256;
            sa[idx >> 7][idx & 127] = fb[(size_t)(kc + (idx >> 7)) * (HW * HW) + (idx & 127)];
        }
#pragma unroll
        for (int r = 0; r < 8; r++) {
            int idx = tid + r * 256;
            int o = idx >> 4, k = idx & 15;
            sw[k][o] = w[o * CIN + kc + k];
        }
        __syncthreads();
#pragma unroll
        for (int k = 0; k < 16; k++) {
            ulonglong2 a01 = *(const ulonglong2*)&sa[k][ty * 8];
            ulonglong2 a23 = *(const ulonglong2*)&sa[k][ty * 8 + 4];
            float4 w0 = *(const float4*)&sw[k][tx * 8];
            float4 w1 = *(const float4*)&sw[k][tx * 8 + 4];
            u64 av[4] = {a01.x, a01.y, a23.x, a23.y};
            u64 wd[8] = {dup2(w0.x), dup2(w0.y), dup2(w0.z), dup2(w0.w),
                         dup2(w1.x), dup2(w1.y), dup2(w1.z), dup2(w1.w)};
#pragma unroll
            for (int i = 0; i < 4; i++)
#pragma unroll
                for (int j = 0; j < 8; j++) fma2(acc[i][j], av[i], wd[j]);
        }
        __syncthreads();
    }

    float bv[8];
#pragma unroll
    for (int j = 0; j < 8; j++) bv[j] = bias[tx * 8 + j];
#pragma unroll
    for (int i = 0; i < 4; i++) {
        float2 vj[8];
#pragma unroll
        for (int j = 0; j < 8; j++) vj[j] = unpack2(acc[i][j]);
        size_t pix0 = (size_t)pixbase + ty * 8 + 2 * i;
        float* d0 = &g_x[((size_t)b * (HW * HW) + pix0) * DLOI + tx * 8];
        float* d1 = d0 + DLOI;
        *(float4*)d0       = make_float4(vj[0].x + bv[0], vj[1].x + bv[1],
                                         vj[2].x + bv[2], vj[3].x + bv[3]);
        *(float4*)(d0 + 4) = make_float4(vj[4].x + bv[4], vj[5].x + bv[5],
                                         vj[6].x + bv[6], vj[7].x + bv[7]);
        *(float4*)d1       = make_float4(vj[0].y + bv[0], vj[1].y + bv[1],
                                         vj[2].y + bv[2], vj[3].y + bv[3]);
        *(float4*)(d1 + 4) = make_float4(vj[4].y + bv[4], vj[5].y + bv[5],
                                         vj[6].y + bv[6], vj[7].y + bv[7]);
    }
}

// ---------------------------------------------------------------------------
// K2: bilinear sampling of 32 points per line + maxpool(4) -> g_xp[n][c][t]
// One block per line, 128 threads (thread = channel).  (unchanged, working)
// ---------------------------------------------------------------------------
__global__ __launch_bounds__(128) void k_sample(const float* __restrict__ lines) {
    __shared__ float swt[4][32];
    __shared__ int   soff[4][32];
    const int n = blockIdx.x;
    const int b = n >> 11;
    const int c = threadIdx.x;
    const float* lp = lines + (size_t)n * 4;

    if (c < 32) {
        int p = c;
        float lam = (float)p * (1.0f / 31.0f);
        float l0x = lp[0], l0y = lp[1], l1x = lp[2], l1y = lp[3];
        float px = l0x * lam + l1x * (1.f - lam) - 0.5f;
        float py = l0y * lam + l1y * (1.f - lam) - 0.5f;
        float px0 = fminf(fmaxf(floorf(px), 0.f), 127.f);
        float py0 = fminf(fmaxf(floorf(py), 0.f), 127.f);
        float px1 = fminf(px0 + 1.f, 127.f);
        float py1 = fminf(py0 + 1.f, 127.f);
        int ix0 = (int)px0, iy0 = (int)py0, ix1 = (int)px1, iy1 = (int)py1;
        swt[0][p] = (px1 - px) * (py1 - py);
        swt[1][p] = (px - px0) * (py1 - py);
        swt[2][p] = (px1 - px) * (py - py0);
        swt[3][p] = (px - px0) * (py - py0);
        soff[0][p] = (ix0 * HW + iy0) * DLOI;
        soff[1][p] = (ix1 * HW + iy0) * DLOI;
        soff[2][p] = (ix0 * HW + iy1) * DLOI;
        soff[3][p] = (ix1 * HW + iy1) * DLOI;
    }
    __syncthreads();

    const float* xb = g_x + (size_t)b * (HW * HW) * DLOI + c;
    float xpv[8];
#pragma unroll
    for (int t = 0; t < 8; t++) {
        float m = -3.4e38f;
#pragma unroll
        for (int j = 0; j < 4; j++) {
            int p = t * 4 + j;
            float s = xb[soff[0][p]] * swt[0][p]
                    + xb[soff[1][p]] * swt[1][p]
                    + xb[soff[2][p]] * swt[2][p]
                    + xb[soff[3][p]] * swt[3][p];
            m = fmaxf(m, s);
        }
        xpv[t] = m;
    }
    float* dst = g_xp + (size_t)n * (DLOI * 8) + c * 8;
    *(float4*)dst       = make_float4(xpv[0], xpv[1], xpv[2], xpv[3]);
    *(float4*)(dst + 4) = make_float4(xpv[4], xpv[5], xpv[6], xpv[7]);
}

// ---------------------------------------------------------------------------
// K3: Bottleneck1D + residual + fc2.  8 lines per block, 512 threads, f32x2.
// ---------------------------------------------------------------------------
// smem layout (float offsets)
#define OF_W1    0        // 8192  w1s[c*64 + p]
#define OF_W2    8192     // 12288 w2s[(i*3+dt)*64 + q]
#define OF_W3    20480    // 8192  w3s[q*128 + o]
#define OF_XP    28672    // 8192  xp_s[ln][c][t]
#define OF_A     36864    // 8192  a_s = relu(bn1(xp));  reused as RED later
#define OF_RED   36864    // alias (A dead after conv1)
#define OF_B     45056    // 6144  b_s[ln][p][12] (12-pad, 16B-aligned rows)
#define OF_C     51200    // 4096  c_s[ln][q][8]
#define OF_CONST 55296    // 1792
#define K3_SMEM_FLOATS 57088
#define K3_SMEM_BYTES  (K3_SMEM_FLOATS * 4)
// const sub-offsets: c1b@0, s2@64, o2@128, c2b@192, s3@256, o3@320,
//                    c3b@384, s1@512, o1@640, fc2w@768

__global__ void __launch_bounds__(512, 1) k_bottleneck(
    const float* __restrict__ bn1g, const float* __restrict__ bn1b,
    const float* __restrict__ bn1m, const float* __restrict__ bn1v,
    const float* __restrict__ c1w,  const float* __restrict__ c1b,
    const float* __restrict__ bn2g, const float* __restrict__ bn2b,
    const float* __restrict__ bn2m, const float* __restrict__ bn2v,
    const float* __restrict__ c2w,  const float* __restrict__ c2b,
    const float* __restrict__ bn3g, const float* __restrict__ bn3b,
    const float* __restrict__ bn3m, const float* __restrict__ bn3v,
    const float* __restrict__ c3w,  const float* __restrict__ c3b,
    const float* __restrict__ fc2w, const float* __restrict__ fc2b,
    float* __restrict__ out)
{
    extern __shared__ float sm[];
    const int tid = threadIdx.x;
    const int n0 = blockIdx.x * 8;

    // ---- stage weights (transposed for lane-contiguous reads) ----
#pragma unroll
    for (int r = 0; r < 16; r++) {
        int idx = tid + r * 512;                     // [p][c] -> [c][p]
        sm[OF_W1 + (idx & 127) * 64 + (idx >> 7)] = c1w[idx];
    }
#pragma unroll
    for (int r = 0; r < 24; r++) {
        int idx = tid + r * 512;                     // [q][i][dt] -> [(i*3+dt)][q]
        int q = idx / 192;
        int rem = idx - q * 192;
        sm[OF_W2 + rem * 64 + q] = c2w[idx];
    }
#pragma unroll
    for (int r = 0; r < 16; r++) {
        int idx = tid + r * 512;                     // [o][q] -> [q][o]
        sm[OF_W3 + (idx & 63) * 128 + (idx >> 6)] = c3w[idx];
    }
    // ---- stage consts ----
    if (tid < 64) {
        float s2 = bn2g[tid] * rsqrtf(bn2v[tid] + BN_EPS);
        sm[OF_CONST + 64 + tid]  = s2;
        sm[OF_CONST + 128 + tid] = bn2b[tid] - bn2m[tid] * s2;
        sm[OF_CONST + 0 + tid]   = c1b[tid];
        float s3 = bn3g[tid] * rsqrtf(bn3v[tid] + BN_EPS);
        sm[OF_CONST + 256 + tid] = s3;
        sm[OF_CONST + 320 + tid] = bn3b[tid] - bn3m[tid] * s3;
        sm[OF_CONST + 192 + tid] = c2b[tid];
    }
    if (tid < 128) {
        sm[OF_CONST + 384 + tid] = c3b[tid];
        float s1 = bn1g[tid] * rsqrtf(bn1v[tid] + BN_EPS);
        sm[OF_CONST + 512 + tid] = s1;
        sm[OF_CONST + 640 + tid] = bn1b[tid] - bn1m[tid] * s1;
    }
#pragma unroll
    for (int r = 0; r < 2; r++)
        sm[OF_CONST + 768 + tid + r * 512] = fc2w[tid + r * 512];

    // ---- stage xp (8 lines) ----
    {
        const float4* src = (const float4*)(g_xp + (size_t)n0 * (DLOI * 8));
        float4* dst = (float4*)(sm + OF_XP);
#pragma unroll
        for (int r = 0; r < 4; r++) dst[tid + r * 512] = src[tid + r * 512];
    }
    __syncthreads();

    // ---- a_s = relu(bn1(xp)) ----
#pragma unroll
    for (int r = 0; r < 16; r++) {
        int idx = tid + r * 512;            // [ln][c][t]
        int cch = (idx >> 3) & 127;
        float v = sm[OF_XP + idx] * sm[OF_CONST + 512 + cch] + sm[OF_CONST + 640 + cch];
        sm[OF_A + idx] = fmaxf(v, 0.f);
    }
    __syncthreads();

    // ---- conv1 (128->64) + bias + bn2 + relu -> b_s (f32x2 over t pairs) ----
    {
        int p = tid & 63, ln = tid >> 6;
        u64 acc[4] = {0ULL, 0ULL, 0ULL, 0ULL};
        const ulonglong2* Abase = (const ulonglong2*)(sm + OF_A + (size_t)ln * 128 * 8);
#pragma unroll 4
        for (int cc = 0; cc < 128; cc++) {
            u64 wd = dup2(sm[OF_W1 + cc * 64 + p]);
            ulonglong2 u0 = Abase[cc * 2];
            ulonglong2 u1 = Abase[cc * 2 + 1];
            fma2(acc[0], wd, u0.x);
            fma2(acc[1], wd, u0.y);
            fma2(acc[2], wd, u1.x);
            fma2(acc[3], wd, u1.y);
        }
        float s2 = sm[OF_CONST + 64 + p], o2 = sm[OF_CONST + 128 + p];
        float bb = sm[OF_CONST + p];
        float* Brow = sm + OF_B + (ln * 64 + p) * 12;
        Brow[0] = 0.f; Brow[9] = 0.f;
#pragma unroll
        for (int pr = 0; pr < 4; pr++) {
            float2 v = unpack2(acc[pr]);
            Brow[1 + 2 * pr]     = fmaxf((v.x + bb) * s2 + o2, 0.f);
            Brow[1 + 2 * pr + 1] = fmaxf((v.y + bb) * s2 + o2, 0.f);
        }
    }
    __syncthreads();

    // ---- conv2 (3-tap, 64->64) + bias + bn3 + relu -> c_s ----
    {
        int q = tid & 63, ln = tid >> 6;
        float acc[8];
#pragma unroll
        for (int t = 0; t < 8; t++) acc[t] = 0.f;
#pragma unroll 2
        for (int i = 0; i < 64; i++) {
            float w0  = sm[OF_W2 + (i * 3 + 0) * 64 + q];
            float w1v = sm[OF_W2 + (i * 3 + 1) * 64 + q];
            float w2v = sm[OF_W2 + (i * 3 + 2) * 64 + q];
            const float* Br = sm + OF_B + (ln * 64 + i) * 12;
            float4 x0 = *(const float4*)Br;
            float4 x1 = *(const float4*)(Br + 4);
            float2 x2 = *(const float2*)(Br + 8);
            float in[10] = {x0.x, x0.y, x0.z, x0.w, x1.x, x1.y, x1.z, x1.w, x2.x, x2.y};
#pragma unroll
            for (int t = 0; t < 8; t++)
                acc[t] += w0 * in[t] + w1v * in[t + 1] + w2v * in[t + 2];
        }
        float s3 = sm[OF_CONST + 256 + q], o3v = sm[OF_CONST + 320 + q];
        float bb = sm[OF_CONST + 192 + q];
        float* Crow = sm + OF_C + (ln * 64 + q) * 8;
#pragma unroll
        for (int t = 0; t < 8; t++)
            Crow[t] = fmaxf((acc[t] + bb) * s3 + o3v, 0.f);
    }
    __syncthreads();

    // ---- conv3 (64->128) + residual + relu + fc2 partial (f32x2) ----
    {
        int o = tid & 127, g = tid >> 7;         // lines {g, g+4}
        u64 acc[2][4];
#pragma unroll
        for (int a = 0; a < 2; a++)
#pragma unroll
            for (int pr = 0; pr < 4; pr++) acc[a][pr] = 0ULL;
#pragma unroll 2
        for (int q = 0; q < 64; q++) {
            u64 wd = dup2(sm[OF_W3 + q * 128 + o]);
#pragma unroll
            for (int k = 0; k < 2; k++) {
                const ulonglong2* Crow =
                    (const ulonglong2*)(sm + OF_C + ((g + 4 * k) * 64 + q) * 8);
                ulonglong2 u0 = Crow[0];
                ulonglong2 u1 = Crow[1];
                fma2(acc[k][0], wd, u0.x);
                fma2(acc[k][1], wd, u0.y);
                fma2(acc[k][2], wd, u1.x);
                fma2(acc[k][3], wd, u1.y);
            }
        }
        float bb = sm[OF_CONST + 384 + o];
        float fw[8];
#pragma unroll
        for (int t = 0; t < 8; t++) fw[t] = sm[OF_CONST + 768 + o * 8 + t];
#pragma unroll
        for (int k = 0; k < 2; k++) {
            int ln = g + 4 * k;
            const float* X = sm + OF_XP + (ln * 128 + o) * 8;
            float lsum = 0.f;
#pragma unroll
            for (int pr = 0; pr < 4; pr++) {
                float2 v = unpack2(acc[k][pr]);
                float v0 = fmaxf(X[2 * pr]     + v.x + bb, 0.f);
                float v1 = fmaxf(X[2 * pr + 1] + v.y + bb, 0.f);
                lsum += v0 * fw[2 * pr] + v1 * fw[2 * pr + 1];
            }
            sm[OF_RED + ln * 128 + o] = lsum;
        }
    }
    __syncthreads();

    // ---- reduce 128 partials per line, write logits ----
    if (tid < 256) {
        int ln = tid >> 5, lane = tid & 31;
        float s = sm[OF_RED + ln * 128 + lane]
                + sm[OF_RED + ln * 128 + lane + 32]
                + sm[OF_RED + ln * 128 + lane + 64]
                + sm[OF_RED + ln * 128 + lane + 96];
#pragma unroll
        for (int off = 16; off > 0; off >>= 1)
            s += __shfl_xor_sync(0xffffffffu, s, off);
        if (lane == 0) out[n0 + ln] = s + fc2b[0];
    }
}

// ---------------------------------------------------------------------------
extern "C" void kernel_launch(void* const* d_in, const int* in_sizes, int n_in,
                              void* d_out, int out_size) {
    const float* feature = (const float*)d_in[0];
    const float* lines   = (const float*)d_in[1];
    const float* fc1_w   = (const float*)d_in[2];
    const float* fc1_b   = (const float*)d_in[3];
    const float* bn1g = (const float*)d_in[4];
    const float* bn1b = (const float*)d_in[5];
    const float* bn1m = (const float*)d_in[6];
    const float* bn1v = (const float*)d_in[7];
    const float* c1w  = (const float*)d_in[8];
    const float* c1b  = (const float*)d_in[9];
    const float* bn2g = (const float*)d_in[10];
    const float* bn2b = (const float*)d_in[11];
    const float* bn2m = (const float*)d_in[12];
    const float* bn2v = (const float*)d_in[13];
    const float* c2w  = (const float*)d_in[14];
    const float* c2b  = (const float*)d_in[15];
    const float* bn3g = (const float*)d_in[16];
    const float* bn3b = (const float*)d_in[17];
    const float* bn3m = (const float*)d_in[18];
    const float* bn3v = (const float*)d_in[19];
    const float* c3w  = (const float*)d_in[20];
    const float* c3b  = (const float*)d_in[21];
    const float* fc2w = (const float*)d_in[22];
    const float* fc2b = (const float*)d_in[23];
    float* out = (float*)d_out;

    cudaFuncSetAttribute(k_bottleneck,
                         cudaFuncAttributeMaxDynamicSharedMemorySize,
                         K3_SMEM_BYTES);

    dim3 g1(HW * HW / 128, NB);
    k_fc1<<<g1, 256>>>(feature, fc1_w, fc1_b);
    k_sample<<<NLINES, 128>>>(lines);
    k_bottleneck<<<NLINES / 8, 512, K3_SMEM_BYTES>>>(
        bn1g, bn1b, bn1m, bn1v, c1w, c1b,
        bn2g, bn2b, bn2m, bn2v, c2w, c2b,
        bn3g, bn3b, bn3m, bn3v, c3w, c3b,
        fc2w, fc2b, out);
}

// round 3
// speedup vs baseline: 1.1547x; 1.0060x over previous
#include <cuda_runtime.h>
#include <math.h>

#define HW    128
#define CIN   256
#define DLOI  128
#define NB    8
#define NL    2048
#define NLINES (NB*NL)
#define BN_EPS 1e-5f

// Scratch: fc1 output in NHWC layout [b][i][j][o]  (64 MB)
__device__ float g_x[(size_t)NB * HW * HW * DLOI];

// ---- packed f32x2 helpers (sm_103a dual-fp32 pipe) ----
typedef unsigned long long u64;

__device__ __forceinline__ u64 dup2(float x) {
    u64 r; asm("mov.b64 %0, {%1, %1};" : "=l"(r) : "f"(x)); return r;
}
__device__ __forceinline__ float2 unpack2(u64 v) {
    float2 f; asm("mov.b64 {%0, %1}, %2;" : "=f"(f.x), "=f"(f.y) : "l"(v)); return f;
}
__device__ __forceinline__ void fma2(u64& d, u64 a, u64 b) {
    asm("fma.rn.f32x2 %0, %1, %2, %0;" : "+l"(d) : "l"(a), "l"(b));
}
__device__ __forceinline__ void cp16(void* smem_dst, const void* gsrc) {
    unsigned s = (unsigned)__cvta_generic_to_shared(smem_dst);
    asm volatile("cp.async.ca.shared.global [%0], [%1], 16;" :: "r"(s), "l"(gsrc) : "memory");
}
__device__ __forceinline__ void cp_commit() {
    asm volatile("cp.async.commit_group;" ::: "memory");
}

// ---------------------------------------------------------------------------
// K1: fc1 1x1 conv as SGEMM with f32x2, cp.async 3-stage pipeline.
// Block tile 128 pix x 128 out, 256 threads, thread tile 8pix x 8out.
// A (feature tile) via cp.async; W stored PRE-DUPLICATED in a bank-conflict-
// free layout (column = (o>>3)*20 + (o&7)*2).
// ---------------------------------------------------------------------------
#define KT 16
#define NT (CIN / KT)         // 16 k-tiles
#define SA_OF(s,k) ((s)*2048 + (k)*128)          // 3 * 16*128
#define SW_OF(s,k) (6144 + (s)*5120 + (k)*320)   // 3 * 16*320 (dup'd, stride 20/txgroup)
#define FC1_SMEM_FLOATS (6144 + 3*5120)          // 21504 floats = 84 KB
#define FC1_SMEM_BYTES  (FC1_SMEM_FLOATS * 4)

__global__ __launch_bounds__(256, 2) void k_fc1(const float* __restrict__ feat,
                                                const float* __restrict__ w,
                                                const float* __restrict__ bias) {
    extern __shared__ float smem[];
    const int b = blockIdx.y;
    const int pixbase = blockIdx.x * 128;
    const int tid = threadIdx.x;
    const int tx = tid & 15;    // out group: o0 = tx*8
    const int ty = tid >> 4;    // pix group: p0 = ty*8

    const float* fb = feat + (size_t)b * CIN * HW * HW + pixbase;

    // per-thread A cp.async coords (2 chunks)
    const int ar0 = tid >> 5, ac0 = (tid & 31) * 4;
    const int ar1 = (tid + 256) >> 5, ac1 = ((tid + 256) & 31) * 4;
    // per-thread W coords (2 float4 rows)
    const int wo0 = tid >> 2, wq0 = tid & 3;
    const int wo1 = (tid + 256) >> 2, wq1 = (tid + 256) & 3;

    u64 acc[4][8];
#pragma unroll
    for (int i = 0; i < 4; i++)
#pragma unroll
        for (int j = 0; j < 8; j++) acc[i][j] = 0ULL;

    // ---- prefetch helpers (macros to keep registers simple) ----
#define PREF_A(t, s) do {                                                     \
        cp16(smem + SA_OF(s, ar0) + ac0, fb + (size_t)((t)*KT + ar0)*(HW*HW) + ac0); \
        cp16(smem + SA_OF(s, ar1) + ac1, fb + (size_t)((t)*KT + ar1)*(HW*HW) + ac1); \
    } while (0)
#define PREF_W(t, s) do {                                                     \
        float4 v0 = *(const float4*)(w + (size_t)wo0*CIN + (t)*KT + wq0*4);   \
        float4 v1 = *(const float4*)(w + (size_t)wo1*CIN + (t)*KT + wq1*4);   \
        int col0 = (wo0 >> 3)*20 + (wo0 & 7)*2;                               \
        int col1 = (wo1 >> 3)*20 + (wo1 & 7)*2;                               \
        float* p0 = smem + SW_OF(s, wq0*4) + col0;                            \
        float* p1 = smem + SW_OF(s, wq1*4) + col1;                            \
        *(float2*)(p0)       = make_float2(v0.x, v0.x);                       \
        *(float2*)(p0 + 320) = make_float2(v0.y, v0.y);                       \
        *(float2*)(p0 + 640) = make_float2(v0.z, v0.z);                       \
        *(float2*)(p0 + 960) = make_float2(v0.w, v0.w);                       \
        *(float2*)(p1)       = make_float2(v1.x, v1.x);                       \
        *(float2*)(p1 + 320) = make_float2(v1.y, v1.y);                       \
        *(float2*)(p1 + 640) = make_float2(v1.z, v1.z);                       \
        *(float2*)(p1 + 960) = make_float2(v1.w, v1.w);                       \
    } while (0)

    // prologue: stages 0 and 1
    PREF_W(0, 0); PREF_A(0, 0); cp_commit();
    PREF_W(1, 1); PREF_A(1, 1); cp_commit();

#pragma unroll 1
    for (int t = 0; t < NT; t++) {
        if (t < NT - 1)
            asm volatile("cp.async.wait_group 1;" ::: "memory");
        else
            asm volatile("cp.async.wait_group 0;" ::: "memory");
        __syncthreads();
        if (t + 2 < NT) {
            int s = (t + 2) % 3;
            PREF_W(t + 2, s); PREF_A(t + 2, s); cp_commit();
        }
        const int s = t % 3;
#pragma unroll
        for (int k = 0; k < KT; k++) {
            const ulonglong2* ap = (const ulonglong2*)(smem + SA_OF(s, k) + ty * 8);
            ulonglong2 a01 = ap[0], a23 = ap[1];
            const ulonglong2* wp = (const ulonglong2*)(smem + SW_OF(s, k) + tx * 20);
            ulonglong2 q0 = wp[0], q1 = wp[1], q2 = wp[2], q3 = wp[3];
            u64 av[4] = {a01.x, a01.y, a23.x, a23.y};
            u64 wd[8] = {q0.x, q0.y, q1.x, q1.y, q2.x, q2.y, q3.x, q3.y};
#pragma unroll
            for (int i = 0; i < 4; i++)
#pragma unroll
                for (int j = 0; j < 8; j++) fma2(acc[i][j], av[i], wd[j]);
        }
    }
#undef PREF_A
#undef PREF_W

    float bv[8];
#pragma unroll
    for (int j = 0; j < 8; j++) bv[j] = bias[tx * 8 + j];
#pragma unroll
    for (int i = 0; i < 4; i++) {
        float2 vj[8];
#pragma unroll
        for (int j = 0; j < 8; j++) vj[j] = unpack2(acc[i][j]);
        size_t pix0 = (size_t)pixbase + ty * 8 + 2 * i;
        float* d0 = &g_x[((size_t)b * (HW * HW) + pix0) * DLOI + tx * 8];
        float* d1 = d0 + DLOI;
        *(float4*)d0       = make_float4(vj[0].x + bv[0], vj[1].x + bv[1],
                                         vj[2].x + bv[2], vj[3].x + bv[3]);
        *(float4*)(d0 + 4) = make_float4(vj[4].x + bv[4], vj[5].x + bv[5],
                                         vj[6].x + bv[6], vj[7].x + bv[7]);
        *(float4*)d1       = make_float4(vj[0].y + bv[0], vj[1].y + bv[1],
                                         vj[2].y + bv[2], vj[3].y + bv[3]);
        *(float4*)(d1 + 4) = make_float4(vj[4].y + bv[4], vj[5].y + bv[5],
                                         vj[6].y + bv[6], vj[7].y + bv[7]);
    }
}

// ---------------------------------------------------------------------------
// K2: fused sampling + Bottleneck1D + residual + fc2.
// 8 lines per block, 512 threads.
// ---------------------------------------------------------------------------
// smem layout (float offsets)
#define OF_W1    0        // 8192  w1s[c*64 + p]
#define OF_W2    8192     // 12288 w2s[(i*3+dt)*64 + q]
#define OF_W3    20480    // 8192  w3s[q*128 + o]
#define OF_XP    28672    // 8192  xp_s[ln][c][t]
#define OF_A     36864    // 8192  a_s = relu(bn1(xp));  reused as RED later
#define OF_RED   36864    // alias (A dead after conv1)
#define OF_B     45056    // 6144  b_s[ln][p][12]; aliases sampling tables first
#define OF_C     51200    // 4096  c_s[ln][q][8]
#define OF_CONST 55296    // 1792
#define K3_SMEM_FLOATS 57088
#define K3_SMEM_BYTES  (K3_SMEM_FLOATS * 4)
// const sub-offsets: c1b@0, s2@64, o2@128, c2b@192, s3@256, o3@320,
//                    c3b@384, s1@512, o1@640, fc2w@768

__global__ void __launch_bounds__(512, 1) k_lines(
    const float* __restrict__ lines,
    const float* __restrict__ bn1g, const float* __restrict__ bn1b,
    const float* __restrict__ bn1m, const float* __restrict__ bn1v,
    const float* __restrict__ c1w,  const float* __restrict__ c1b,
    const float* __restrict__ bn2g, const float* __restrict__ bn2b,
    const float* __restrict__ bn2m, const float* __restrict__ bn2v,
    const float* __restrict__ c2w,  const float* __restrict__ c2b,
    const float* __restrict__ bn3g, const float* __restrict__ bn3b,
    const float* __restrict__ bn3m, const float* __restrict__ bn3v,
    const float* __restrict__ c3w,  const float* __restrict__ c3b,
    const float* __restrict__ fc2w, const float* __restrict__ fc2b,
    float* __restrict__ out)
{
    extern __shared__ float sm[];
    const int tid = threadIdx.x;
    const int n0 = blockIdx.x * 8;

    // ---- stage weights (transposed for lane-contiguous reads) ----
#pragma unroll
    for (int r = 0; r < 16; r++) {
        int idx = tid + r * 512;                     // [p][c] -> [c][p]
        sm[OF_W1 + (idx & 127) * 64 + (idx >> 7)] = c1w[idx];
    }
#pragma unroll
    for (int r = 0; r < 24; r++) {
        int idx = tid + r * 512;                     // [q][i][dt] -> [(i*3+dt)][q]
        int q = idx / 192;
        int rem = idx - q * 192;
        sm[OF_W2 + rem * 64 + q] = c2w[idx];
    }
#pragma unroll
    for (int r = 0; r < 16; r++) {
        int idx = tid + r * 512;                     // [o][q] -> [q][o]
        sm[OF_W3 + (idx & 63) * 128 + (idx >> 6)] = c3w[idx];
    }
    // ---- stage consts ----
    if (tid < 64) {
        float s2 = bn2g[tid] * rsqrtf(bn2v[tid] + BN_EPS);
        sm[OF_CONST + 64 + tid]  = s2;
        sm[OF_CONST + 128 + tid] = bn2b[tid] - bn2m[tid] * s2;
        sm[OF_CONST + 0 + tid]   = c1b[tid];
        float s3 = bn3g[tid] * rsqrtf(bn3v[tid] + BN_EPS);
        sm[OF_CONST + 256 + tid] = s3;
        sm[OF_CONST + 320 + tid] = bn3b[tid] - bn3m[tid] * s3;
        sm[OF_CONST + 192 + tid] = c2b[tid];
    }
    if (tid < 128) {
        sm[OF_CONST + 384 + tid] = c3b[tid];
        float s1 = bn1g[tid] * rsqrtf(bn1v[tid] + BN_EPS);
        sm[OF_CONST + 512 + tid] = s1;
        sm[OF_CONST + 640 + tid] = bn1b[tid] - bn1m[tid] * s1;
    }
#pragma unroll
    for (int r = 0; r < 2; r++)
        sm[OF_CONST + 768 + tid + r * 512] = fc2w[tid + r * 512];

    // ---- sampling tables (aliased in OF_B region, dead before conv1) ----
    if (tid < 256) {
        int ln = tid >> 5, p = tid & 31;
        const float* lp = lines + (size_t)(n0 + ln) * 4;
        float lam = (float)p * (1.0f / 31.0f);
        float px = lp[0] * lam + lp[2] * (1.f - lam) - 0.5f;
        float py = lp[1] * lam + lp[3] * (1.f - lam) - 0.5f;
        float px0 = fminf(fmaxf(floorf(px), 0.f), 127.f);
        float py0 = fminf(fmaxf(floorf(py), 0.f), 127.f);
        float px1 = fminf(px0 + 1.f, 127.f);
        float py1 = fminf(py0 + 1.f, 127.f);
        int ix0 = (int)px0, iy0 = (int)py0, ix1 = (int)px1, iy1 = (int)py1;
        sm[OF_B + 0 * 256 + tid] = (px1 - px) * (py1 - py);
        sm[OF_B + 1 * 256 + tid] = (px - px0) * (py1 - py);
        sm[OF_B + 2 * 256 + tid] = (px1 - px) * (py - py0);
        sm[OF_B + 3 * 256 + tid] = (px - px0) * (py - py0);
        int* ofb = (int*)(sm + OF_B + 1024);
        ofb[0 * 256 + tid] = (ix0 * HW + iy0) * (DLOI / 2);   // in u64 units
        ofb[1 * 256 + tid] = (ix1 * HW + iy0) * (DLOI / 2);
        ofb[2 * 256 + tid] = (ix0 * HW + iy1) * (DLOI / 2);
        ofb[3 * 256 + tid] = (ix1 * HW + iy1) * (DLOI / 2);
    }
    __syncthreads();

    // ---- sampling: 8 lines x 128 ch, thread = (ln, channel-pair) ----
    {
        int ln = tid >> 6, cp = tid & 63, c0 = cp * 2;
        int bb = n0 >> 11;   // batch (2048 lines per image, block never straddles)
        const u64* basep = (const u64*)g_x + (size_t)bb * (HW * HW) * (DLOI / 2) + cp;
        const float* wtb = sm + OF_B;
        const int*   ofb = (const int*)(sm + OF_B + 1024);
        float v0[8], v1[8];
#pragma unroll
        for (int t = 0; t < 8; t++) {
            float m0 = -3.4e38f, m1 = -3.4e38f;
#pragma unroll
            for (int j = 0; j < 4; j++) {
                int idx = ln * 32 + t * 4 + j;
                u64 acc = 0ULL;
#pragma unroll
                for (int cn = 0; cn < 4; cn++) {
                    float wv = wtb[cn * 256 + idx];
                    u64 xv = basep[ofb[cn * 256 + idx]];
                    fma2(acc, dup2(wv), xv);
                }
                float2 s = unpack2(acc);
                m0 = fmaxf(m0, s.x);
                m1 = fmaxf(m1, s.y);
            }
            v0[t] = m0; v1[t] = m1;
        }
        float* xr = sm + OF_XP + (ln * 128 + c0) * 8;
        *(float4*)xr        = make_float4(v0[0], v0[1], v0[2], v0[3]);
        *(float4*)(xr + 4)  = make_float4(v0[4], v0[5], v0[6], v0[7]);
        *(float4*)(xr + 8)  = make_float4(v1[0], v1[1], v1[2], v1[3]);
        *(float4*)(xr + 12) = make_float4(v1[4], v1[5], v1[6], v1[7]);
    }
    __syncthreads();

    // ---- a_s = relu(bn1(xp)) ----
#pragma unroll
    for (int r = 0; r < 16; r++) {
        int idx = tid + r * 512;            // [ln][c][t]
        int cch = (idx >> 3) & 127;
        float v = sm[OF_XP + idx] * sm[OF_CONST + 512 + cch] + sm[OF_CONST + 640 + cch];
        sm[OF_A + idx] = fmaxf(v, 0.f);
    }
    __syncthreads();

    // ---- conv1 (128->64) + bias + bn2 + relu -> b_s (f32x2 over t pairs) ----
    {
        int p = tid & 63, ln = tid >> 6;
        u64 acc[4] = {0ULL, 0ULL, 0ULL, 0ULL};
        const ulonglong2* Abase = (const ulonglong2*)(sm + OF_A + (size_t)ln * 128 * 8);
#pragma unroll 4
        for (int cc = 0; cc < 128; cc++) {
            u64 wd = dup2(sm[OF_W1 + cc * 64 + p]);
            ulonglong2 u0 = Abase[cc * 2];
            ulonglong2 u1 = Abase[cc * 2 + 1];
            fma2(acc[0], wd, u0.x);
            fma2(acc[1], wd, u0.y);
            fma2(acc[2], wd, u1.x);
            fma2(acc[3], wd, u1.y);
        }
        float s2 = sm[OF_CONST + 64 + p], o2 = sm[OF_CONST + 128 + p];
        float bb = sm[OF_CONST + p];
        float* Brow = sm + OF_B + (ln * 64 + p) * 12;
        Brow[0] = 0.f; Brow[9] = 0.f;
#pragma unroll
        for (int pr = 0; pr < 4; pr++) {
            float2 v = unpack2(acc[pr]);
            Brow[1 + 2 * pr]     = fmaxf((v.x + bb) * s2 + o2, 0.f);
            Brow[1 + 2 * pr + 1] = fmaxf((v.y + bb) * s2 + o2, 0.f);
        }
    }
    __syncthreads();

    // ---- conv2 (3-tap, 64->64) + bias + bn3 + relu -> c_s ----
    {
        int q = tid & 63, ln = tid >> 6;
        float acc[8];
#pragma unroll
        for (int t = 0; t < 8; t++) acc[t] = 0.f;
#pragma unroll 2
        for (int i = 0; i < 64; i++) {
            float w0  = sm[OF_W2 + (i * 3 + 0) * 64 + q];
            float w1v = sm[OF_W2 + (i * 3 + 1) * 64 + q];
            float w2v = sm[OF_W2 + (i * 3 + 2) * 64 + q];
            const float* Br = sm + OF_B + (ln * 64 + i) * 12;
            float4 x0 = *(const float4*)Br;
            float4 x1 = *(const float4*)(Br + 4);
            float2 x2 = *(const float2*)(Br + 8);
            float in[10] = {x0.x, x0.y, x0.z, x0.w, x1.x, x1.y, x1.z, x1.w, x2.x, x2.y};
#pragma unroll
            for (int t = 0; t < 8; t++)
                acc[t] += w0 * in[t] + w1v * in[t + 1] + w2v * in[t + 2];
        }
        float s3 = sm[OF_CONST + 256 + q], o3v = sm[OF_CONST + 320 + q];
        float bb = sm[OF_CONST + 192 + q];
        float* Crow = sm + OF_C + (ln * 64 + q) * 8;
#pragma unroll
        for (int t = 0; t < 8; t++)
            Crow[t] = fmaxf((acc[t] + bb) * s3 + o3v, 0.f);
    }
    __syncthreads();

    // ---- conv3 (64->128) + residual + relu + fc2 partial (f32x2) ----
    {
        int o = tid & 127, g = tid >> 7;         // lines {g, g+4}
        u64 acc[2][4];
#pragma unroll
        for (int a = 0; a < 2; a++)
#pragma unroll
            for (int pr = 0; pr < 4; pr++) acc[a][pr] = 0ULL;
#pragma unroll 2
        for (int q = 0; q < 64; q++) {
            u64 wd = dup2(sm[OF_W3 + q * 128 + o]);
#pragma unroll
            for (int k = 0; k < 2; k++) {
                const ulonglong2* Crow =
                    (const ulonglong2*)(sm + OF_C + ((g + 4 * k) * 64 + q) * 8);
                ulonglong2 u0 = Crow[0];
                ulonglong2 u1 = Crow[1];
                fma2(acc[k][0], wd, u0.x);
                fma2(acc[k][1], wd, u0.y);
                fma2(acc[k][2], wd, u1.x);
                fma2(acc[k][3], wd, u1.y);
            }
        }
        float bb = sm[OF_CONST + 384 + o];
        float fw[8];
#pragma unroll
        for (int t = 0; t < 8; t++) fw[t] = sm[OF_CONST + 768 + o * 8 + t];
#pragma unroll
        for (int k = 0; k < 2; k++) {
            int ln = g + 4 * k;
            const float* X = sm + OF_XP + (ln * 128 + o) * 8;
            float lsum = 0.f;
#pragma unroll
            for (int pr = 0; pr < 4; pr++) {
                float2 v = unpack2(acc[k][pr]);
                float v0 = fmaxf(X[2 * pr]     + v.x + bb, 0.f);
                float v1 = fmaxf(X[2 * pr + 1] + v.y + bb, 0.f);
                lsum += v0 * fw[2 * pr] + v1 * fw[2 * pr + 1];
            }
            sm[OF_RED + ln * 128 + o] = lsum;
        }
    }
    __syncthreads();

    // ---- reduce 128 partials per line, write logits ----
    if (tid < 256) {
        int ln = tid >> 5, lane = tid & 31;
        float s = sm[OF_RED + ln * 128 + lane]
                + sm[OF_RED + ln * 128 + lane + 32]
                + sm[OF_RED + ln * 128 + lane + 64]
                + sm[OF_RED + ln * 128 + lane + 96];
#pragma unroll
        for (int off = 16; off > 0; off >>= 1)
            s += __shfl_xor_sync(0xffffffffu, s, off);
        if (lane == 0) out[n0 + ln] = s + fc2b[0];
    }
}

// ---------------------------------------------------------------------------
extern "C" void kernel_launch(void* const* d_in, const int* in_sizes, int n_in,
                              void* d_out, int out_size) {
    const float* feature = (const float*)d_in[0];
    const float* lines   = (const float*)d_in[1];
    const float* fc1_w   = (const float*)d_in[2];
    const float* fc1_b   = (const float*)d_in[3];
    const float* bn1g = (const float*)d_in[4];
    const float* bn1b = (const float*)d_in[5];
    const float* bn1m = (const float*)d_in[6];
    const float* bn1v = (const float*)d_in[7];
    const float* c1w  = (const float*)d_in[8];
    const float* c1b  = (const float*)d_in[9];
    const float* bn2g = (const float*)d_in[10];
    const float* bn2b = (const float*)d_in[11];
    const float* bn2m = (const float*)d_in[12];
    const float* bn2v = (const float*)d_in[13];
    const float* c2w  = (const float*)d_in[14];
    const float* c2b  = (const float*)d_in[15];
    const float* bn3g = (const float*)d_in[16];
    const float* bn3b = (const float*)d_in[17];
    const float* bn3m = (const float*)d_in[18];
    const float* bn3v = (const float*)d_in[19];
    const float* c3w  = (const float*)d_in[20];
    const float* c3b  = (const float*)d_in[21];
    const float* fc2w = (const float*)d_in[22];
    const float* fc2b = (const float*)d_in[23];
    float* out = (float*)d_out;

    static int configured = 0;
    cudaFuncSetAttribute(k_fc1, cudaFuncAttributeMaxDynamicSharedMemorySize,
                         FC1_SMEM_BYTES);
    cudaFuncSetAttribute(k_lines, cudaFuncAttributeMaxDynamicSharedMemorySize,
                         K3_SMEM_BYTES);
    (void)configured;

    dim3 g1(HW * HW / 128, NB);
    k_fc1<<<g1, 256, FC1_SMEM_BYTES>>>(feature, fc1_w, fc1_b);
    k_lines<<<NLINES / 8, 512, K3_SMEM_BYTES>>>(
        lines,
        bn1g, bn1b, bn1m, bn1v, c1w, c1b,
        bn2g, bn2b, bn2m, bn2v, c2w, c2b,
        bn3g, bn3b, bn3m, bn3v, c3w, c3b,
        fc2w, fc2b, out);
}

// round 5
// speedup vs baseline: 1.7005x; 1.4726x over previous
#include <cuda_runtime.h>
#include <math.h>

#define HW    128
#define CIN   256
#define DLOI  128
#define NB    8
#define NL    2048
#define NLINES (NB*NL)
#define BN_EPS 1e-5f

// Scratch: fc1 output in NHWC layout [b][i][j][o]  (64 MB)
__device__ float g_x[(size_t)NB * HW * HW * DLOI];
// Pre-transformed weights (written by k_prep each launch)
__device__ float g_w1dup[256 * 320];   // fc1 W, dup'd f32x2, conflict-free cols
__device__ float g_w1t[128 * 64];      // conv1 [c][p]
__device__ float g_w2t[192 * 64];      // conv2 [(i*3+dt)][q]
__device__ float g_w3t[64 * 128];      // conv3 [q][o]
__device__ float g_const[1792];        // biases / bn scale+offset / fc2w

// ---- packed f32x2 helpers (sm_103a dual-fp32 pipe) ----
typedef unsigned long long u64;

__device__ __forceinline__ u64 dup2(float x) {
    u64 r; asm("mov.b64 %0, {%1, %1};" : "=l"(r) : "f"(x)); return r;
}
__device__ __forceinline__ float2 unpack2(u64 v) {
    float2 f; asm("mov.b64 {%0, %1}, %2;" : "=f"(f.x), "=f"(f.y) : "l"(v)); return f;
}
__device__ __forceinline__ void fma2(u64& d, u64 a, u64 b) {
    asm("fma.rn.f32x2 %0, %1, %2, %0;" : "+l"(d) : "l"(a), "l"(b));
}
__device__ __forceinline__ void cp16(void* smem_dst, const void* gsrc) {
    unsigned s = (unsigned)__cvta_generic_to_shared(smem_dst);
    asm volatile("cp.async.ca.shared.global [%0], [%1], 16;" :: "r"(s), "l"(gsrc) : "memory");
}
__device__ __forceinline__ void cp_commit() {
    asm volatile("cp.async.commit_group;" ::: "memory");
}

// ---------------------------------------------------------------------------
// K0: weight pre-transform (runs once per launch, trivial cost)
// ---------------------------------------------------------------------------
__global__ void k_prep(const float* __restrict__ fc1w,
                       const float* __restrict__ bn1g, const float* __restrict__ bn1b,
                       const float* __restrict__ bn1m, const float* __restrict__ bn1v,
                       const float* __restrict__ c1w,  const float* __restrict__ c1b,
                       const float* __restrict__ bn2g, const float* __restrict__ bn2b,
                       const float* __restrict__ bn2m, const float* __restrict__ bn2v,
                       const float* __restrict__ c2w,  const float* __restrict__ c2b,
                       const float* __restrict__ bn3g, const float* __restrict__ bn3b,
                       const float* __restrict__ bn3m, const float* __restrict__ bn3v,
                       const float* __restrict__ c3w,  const float* __restrict__ c3b,
                       const float* __restrict__ fc2w) {
    const int tid = blockIdx.x * 256 + threadIdx.x;
    const int STR = gridDim.x * 256;
    for (int i = tid; i < 128 * 256; i += STR) {
        int o = i >> 8, k = i & 255;
        float v = fc1w[i];
        int col = (o >> 3) * 20 + (o & 7) * 2;
        g_w1dup[k * 320 + col]     = v;
        g_w1dup[k * 320 + col + 1] = v;
    }
    for (int i = tid; i < 8192; i += STR) {          // [c][p] <- c1w[p][c]
        int p = i & 63, c = i >> 6;
        g_w1t[i] = c1w[p * 128 + c];
    }
    for (int i = tid; i < 12288; i += STR) {         // [(i3)][q] <- c2w[q][i3]
        int q = i & 63, i3 = i >> 6;
        g_w2t[i] = c2w[q * 192 + i3];
    }
    for (int i = tid; i < 8192; i += STR) {          // [q][o] <- c3w[o][q]
        int o = i & 127, q = i >> 7;
        g_w3t[i] = c3w[o * 64 + q];
    }
    if (tid < 64) {
        float s2 = bn2g[tid] * rsqrtf(bn2v[tid] + BN_EPS);
        g_const[64 + tid]  = s2;
        g_const[128 + tid] = bn2b[tid] - bn2m[tid] * s2;
        g_const[tid]       = c1b[tid];
        float s3 = bn3g[tid] * rsqrtf(bn3v[tid] + BN_EPS);
        g_const[256 + tid] = s3;
        g_const[320 + tid] = bn3b[tid] - bn3m[tid] * s3;
        g_const[192 + tid] = c2b[tid];
    } else if (tid < 192) {
        int t2 = tid - 64;
        g_const[384 + t2] = c3b[t2];
        float s1 = bn1g[t2] * rsqrtf(bn1v[t2] + BN_EPS);
        g_const[512 + t2] = s1;
        g_const[640 + t2] = bn1b[t2] - bn1m[t2] * s1;
    }
    for (int i = tid; i < 1024; i += STR) g_const[768 + i] = fc2w[i];
}

// ---------------------------------------------------------------------------
// K1: fc1 SGEMM, f32x2, ALL staging via cp.async (W pre-dup'd by k_prep).
// Block 128pix x 128out, 256 threads, thread tile 8pix x 8out. 2 blocks/SM.
// W tile = 5120 floats = 1280 x 16B chunks = 5 cp16 per thread.  A tile =
// 2048 floats = 512 chunks = 2 cp16 per thread.
// ---------------------------------------------------------------------------
#define KT 16
#define NT (CIN / KT)
#define SA_OF(s,k) ((s)*2048 + (k)*128)
#define SW_OF(s,k) (6144 + (s)*5120 + (k)*320)
#define FC1_SMEM_FLOATS (6144 + 3*5120)
#define FC1_SMEM_BYTES  (FC1_SMEM_FLOATS * 4)

__global__ __launch_bounds__(256, 2) void k_fc1(const float* __restrict__ feat,
                                                const float* __restrict__ bias) {
    extern __shared__ float smem[];
    const int b = blockIdx.y;
    const int pixbase = blockIdx.x * 128;
    const int tid = threadIdx.x;
    const int tx = tid & 15;
    const int ty = tid >> 4;

    const float* fb = feat + (size_t)b * CIN * HW * HW + pixbase;

    u64 acc[4][8];
#pragma unroll
    for (int i = 0; i < 4; i++)
#pragma unroll
        for (int j = 0; j < 8; j++) acc[i][j] = 0ULL;

#define PREF(t, s) do {                                                        \
        int i0 = tid, i1 = tid + 256;          /* A: 512 chunks of 16B */      \
        cp16(smem + SA_OF(s, i0 >> 5) + (i0 & 31) * 4,                         \
             fb + (size_t)((t)*KT + (i0 >> 5)) * (HW*HW) + (i0 & 31) * 4);     \
        cp16(smem + SA_OF(s, i1 >> 5) + (i1 & 31) * 4,                         \
             fb + (size_t)((t)*KT + (i1 >> 5)) * (HW*HW) + (i1 & 31) * 4);     \
        _Pragma("unroll")                                                      \
        for (int r = 0; r < 5; r++) {          /* W: 1280 chunks of 16B */     \
            int c = tid + r * 256;                                             \
            cp16(smem + SW_OF(s, 0) + c * 4,                                   \
                 g_w1dup + (size_t)(t) * 5120 + c * 4);                        \
        }                                                                      \
    } while (0)

    PREF(0, 0); cp_commit();
    PREF(1, 1); cp_commit();

#pragma unroll 1
    for (int t = 0; t < NT; t++) {
        if (t < NT - 1)
            asm volatile("cp.async.wait_group 1;" ::: "memory");
        else
            asm volatile("cp.async.wait_group 0;" ::: "memory");
        __syncthreads();
        if (t + 2 < NT) {
            int s = (t + 2) % 3;
            PREF(t + 2, s); cp_commit();
        }
        const int s = t % 3;
#pragma unroll
        for (int k = 0; k < KT; k++) {
            const ulonglong2* ap = (const ulonglong2*)(smem + SA_OF(s, k) + ty * 8);
            ulonglong2 a01 = ap[0], a23 = ap[1];
            const ulonglong2* wp = (const ulonglong2*)(smem + SW_OF(s, k) + tx * 20);
            ulonglong2 q0 = wp[0], q1 = wp[1], q2 = wp[2], q3 = wp[3];
            u64 av[4] = {a01.x, a01.y, a23.x, a23.y};
            u64 wd[8] = {q0.x, q0.y, q1.x, q1.y, q2.x, q2.y, q3.x, q3.y};
#pragma unroll
            for (int i = 0; i < 4; i++)
#pragma unroll
                for (int j = 0; j < 8; j++) fma2(acc[i][j], av[i], wd[j]);
        }
        __syncthreads();
    }
#undef PREF

    float bv[8];
#pragma unroll
    for (int j = 0; j < 8; j++) bv[j] = bias[tx * 8 + j];
#pragma unroll
    for (int i = 0; i < 4; i++) {
        float2 vj[8];
#pragma unroll
        for (int j = 0; j < 8; j++) vj[j] = unpack2(acc[i][j]);
        size_t pix0 = (size_t)pixbase + ty * 8 + 2 * i;
        float* d0 = &g_x[((size_t)b * (HW * HW) + pix0) * DLOI + tx * 8];
        float* d1 = d0 + DLOI;
        *(float4*)d0       = make_float4(vj[0].x + bv[0], vj[1].x + bv[1],
                                         vj[2].x + bv[2], vj[3].x + bv[3]);
        *(float4*)(d0 + 4) = make_float4(vj[4].x + bv[4], vj[5].x + bv[5],
                                         vj[6].x + bv[6], vj[7].x + bv[7]);
        *(float4*)d1       = make_float4(vj[0].y + bv[0], vj[1].y + bv[1],
                                         vj[2].y + bv[2], vj[3].y + bv[3]);
        *(float4*)(d1 + 4) = make_float4(vj[4].y + bv[4], vj[5].y + bv[5],
                                         vj[6].y + bv[6], vj[7].y + bv[7]);
    }
}

// ---------------------------------------------------------------------------
// K2: fused sampling + bn1/relu + Bottleneck1D + residual + fc2.
// 4 lines per block, 256 threads, 107KB smem -> 2 blocks/SM.
// Per-phase weight staging into a single shared 12.3K-float region.
// ---------------------------------------------------------------------------
#define L_W     0        // 12288 (W1 8192 / W2 12288 / W3 8192, restaged)
#define L_XP    12288    // 4096  [ln][c][t]
#define L_A     16384    // 4096  a = relu(bn1(xp)); C (2048) aliased here
#define L_C     16384
#define L_B1    20480    // 3072  [ln*64+p]*12, in[0..9] zero-padded; tables/RED alias
#define L_TBL   20480
#define L_RED   20480
#define L_B2    23552    // 2048  [ln*64+p]*8 unpadded copy (for shifted pairs)
#define L_CONST 25600    // 1792
#define K2_SMEM_FLOATS 27392
#define K2_SMEM_BYTES  (K2_SMEM_FLOATS * 4)

__global__ void __launch_bounds__(256, 2) k_lines(
    const float* __restrict__ lines,
    const float* __restrict__ fc2b,
    float* __restrict__ out)
{
    extern __shared__ float sm[];
    const int tid = threadIdx.x;
    const int n0 = blockIdx.x * 4;

    // ---- phase 0: stage W1 + consts + sampling tables ----
    {
        float4* wd = (float4*)(sm + L_W);
        const float4* ws = (const float4*)g_w1t;
#pragma unroll
        for (int r = 0; r < 8; r++) wd[tid + r * 256] = ws[tid + r * 256];
        float4* cd = (float4*)(sm + L_CONST);
        const float4* cs = (const float4*)g_const;
        cd[tid] = cs[tid];
        if (tid < 192) cd[tid + 256] = cs[tid + 256];
    }
    if (tid < 128) {
        int ln = tid >> 5, p = tid & 31;
        const float* lp = lines + (size_t)(n0 + ln) * 4;
        float lam = (float)p * (1.0f / 31.0f);
        float px = lp[0] * lam + lp[2] * (1.f - lam) - 0.5f;
        float py = lp[1] * lam + lp[3] * (1.f - lam) - 0.5f;
        float px0 = fminf(fmaxf(floorf(px), 0.f), 127.f);
        float py0 = fminf(fmaxf(floorf(py), 0.f), 127.f);
        float px1 = fminf(px0 + 1.f, 127.f);
        float py1 = fminf(py0 + 1.f, 127.f);
        int ix0 = (int)px0, iy0 = (int)py0, ix1 = (int)px1, iy1 = (int)py1;
        sm[L_TBL + 0 * 128 + tid] = (px1 - px) * (py1 - py);
        sm[L_TBL + 1 * 128 + tid] = (px - px0) * (py1 - py);
        sm[L_TBL + 2 * 128 + tid] = (px1 - px) * (py - py0);
        sm[L_TBL + 3 * 128 + tid] = (px - px0) * (py - py0);
        int* ofb = (int*)(sm + L_TBL + 512);
        ofb[0 * 128 + tid] = (ix0 * HW + iy0) * (DLOI / 2);
        ofb[1 * 128 + tid] = (ix1 * HW + iy0) * (DLOI / 2);
        ofb[2 * 128 + tid] = (ix0 * HW + iy1) * (DLOI / 2);
        ofb[3 * 128 + tid] = (ix1 * HW + iy1) * (DLOI / 2);
    }
    __syncthreads();

    // ---- sampling + maxpool + fused bn1/relu ----
    {
        int ln = tid >> 6, cp = tid & 63, c0 = cp * 2;
        int bb = n0 >> 11;
        const u64* basep = (const u64*)g_x + (size_t)bb * (HW * HW) * (DLOI / 2) + cp;
        const float* wtb = sm + L_TBL;
        const int*   ofb = (const int*)(sm + L_TBL + 512);
        float v0[8], v1[8];
#pragma unroll
        for (int t = 0; t < 8; t++) {
            float m0 = -3.4e38f, m1 = -3.4e38f;
#pragma unroll
            for (int j = 0; j < 4; j++) {
                int idx = ln * 32 + t * 4 + j;
                u64 acc = 0ULL;
#pragma unroll
                for (int cn = 0; cn < 4; cn++) {
                    float wv = wtb[cn * 128 + idx];
                    u64 xv = basep[ofb[cn * 128 + idx]];
                    fma2(acc, dup2(wv), xv);
                }
                float2 s = unpack2(acc);
                m0 = fmaxf(m0, s.x);
                m1 = fmaxf(m1, s.y);
            }
            v0[t] = m0; v1[t] = m1;
        }
        float s1a = sm[L_CONST + 512 + c0],     o1a = sm[L_CONST + 640 + c0];
        float s1b = sm[L_CONST + 512 + c0 + 1], o1b = sm[L_CONST + 640 + c0 + 1];
        float* xr = sm + L_XP + (ln * 128 + c0) * 8;
        float* ar = sm + L_A  + (ln * 128 + c0) * 8;
        *(float4*)xr        = make_float4(v0[0], v0[1], v0[2], v0[3]);
        *(float4*)(xr + 4)  = make_float4(v0[4], v0[5], v0[6], v0[7]);
        *(float4*)(xr + 8)  = make_float4(v1[0], v1[1], v1[2], v1[3]);
        *(float4*)(xr + 12) = make_float4(v1[4], v1[5], v1[6], v1[7]);
#pragma unroll
        for (int t = 0; t < 8; t++) {
            ar[t]     = fmaxf(v0[t] * s1a + o1a, 0.f);
            ar[8 + t] = fmaxf(v1[t] * s1b + o1b, 0.f);
        }
    }
    __syncthreads();

    // ---- conv1 (128->64) + bias + bn2 + relu -> B1 (padded) + B2 (plain) ----
    {
        int p = tid & 63, ln = tid >> 6;
        u64 acc[4] = {0ULL, 0ULL, 0ULL, 0ULL};
        const ulonglong2* Abase = (const ulonglong2*)(sm + L_A + (size_t)ln * 128 * 8);
#pragma unroll 4
        for (int cc = 0; cc < 128; cc++) {
            u64 wd = dup2(sm[L_W + cc * 64 + p]);
            ulonglong2 u0 = Abase[cc * 2];
            ulonglong2 u1 = Abase[cc * 2 + 1];
            fma2(acc[0], wd, u0.x);
            fma2(acc[1], wd, u0.y);
            fma2(acc[2], wd, u1.x);
            fma2(acc[3], wd, u1.y);
        }
        float s2 = sm[L_CONST + 64 + p], o2 = sm[L_CONST + 128 + p];
        float bb = sm[L_CONST + p];
        float* B1row = sm + L_B1 + (ln * 64 + p) * 12;
        float* B2row = sm + L_B2 + (ln * 64 + p) * 8;
        B1row[0] = 0.f; B1row[9] = 0.f;
#pragma unroll
        for (int pr = 0; pr < 4; pr++) {
            float2 v = unpack2(acc[pr]);
            float va = fmaxf((v.x + bb) * s2 + o2, 0.f);
            float vb = fmaxf((v.y + bb) * s2 + o2, 0.f);
            B1row[1 + 2 * pr] = va;
            B1row[2 + 2 * pr] = vb;
            *(float2*)(B2row + 2 * pr) = make_float2(va, vb);
        }
    }
    __syncthreads();

    // ---- stage W2 ----
    {
        float4* wd = (float4*)(sm + L_W);
        const float4* ws = (const float4*)g_w2t;
#pragma unroll
        for (int r = 0; r < 12; r++) wd[tid + r * 256] = ws[tid + r * 256];
    }
    __syncthreads();

    // ---- conv2 (3-tap, 64->64) f32x2 + bias + bn3 + relu -> C ----
    {
        int q = tid & 63, ln = tid >> 6;
        u64 acc2[4] = {0ULL, 0ULL, 0ULL, 0ULL};
#pragma unroll 2
        for (int i = 0; i < 64; i++) {
            u64 W0 = dup2(sm[L_W + (i * 3 + 0) * 64 + q]);
            u64 W1 = dup2(sm[L_W + (i * 3 + 1) * 64 + q]);
            u64 W2 = dup2(sm[L_W + (i * 3 + 2) * 64 + q]);
            const float* Br = sm + L_B1 + (ln * 64 + i) * 12;
            ulonglong2 pA = *(const ulonglong2*)Br;
            ulonglong2 pB = *(const ulonglong2*)(Br + 4);
            u64 P4 = *(const u64*)(Br + 8);
            const ulonglong2* Qr = (const ulonglong2*)(sm + L_B2 + (ln * 64 + i) * 8);
            ulonglong2 qA = Qr[0], qB = Qr[1];
            u64 P[5] = {pA.x, pA.y, pB.x, pB.y, P4};
            u64 Q[4] = {qA.x, qA.y, qB.x, qB.y};
#pragma unroll
            for (int pr = 0; pr < 4; pr++) {
                fma2(acc2[pr], W0, P[pr]);
                fma2(acc2[pr], W1, Q[pr]);
                fma2(acc2[pr], W2, P[pr + 1]);
            }
        }
        float s3 = sm[L_CONST + 256 + q], o3v = sm[L_CONST + 320 + q];
        float bb = sm[L_CONST + 192 + q];
        float* Crow = sm + L_C + (ln * 64 + q) * 8;
#pragma unroll
        for (int pr = 0; pr < 4; pr++) {
            float2 v = unpack2(acc2[pr]);
            Crow[2 * pr]     = fmaxf((v.x + bb) * s3 + o3v, 0.f);
            Crow[2 * pr + 1] = fmaxf((v.y + bb) * s3 + o3v, 0.f);
        }
    }
    __syncthreads();

    // ---- stage W3 ----
    {
        float4* wd = (float4*)(sm + L_W);
        const float4* ws = (const float4*)g_w3t;
#pragma unroll
        for (int r = 0; r < 8; r++) wd[tid + r * 256] = ws[tid + r * 256];
    }
    __syncthreads();

    // ---- conv3 (64->128) + residual + relu + fc2 partial ----
    {
        int o = tid & 63, ln = tid >> 6;         // handles o and o+64
        u64 acc[2][4];
#pragma unroll
        for (int a = 0; a < 2; a++)
#pragma unroll
            for (int pr = 0; pr < 4; pr++) acc[a][pr] = 0ULL;
#pragma unroll 2
        for (int q = 0; q < 64; q++) {
            u64 w0 = dup2(sm[L_W + q * 128 + o]);
            u64 w1 = dup2(sm[L_W + q * 128 + o + 64]);
            const ulonglong2* Crow = (const ulonglong2*)(sm + L_C + (ln * 64 + q) * 8);
            ulonglong2 u0 = Crow[0], u1 = Crow[1];
            fma2(acc[0][0], w0, u0.x); fma2(acc[0][1], w0, u0.y);
            fma2(acc[0][2], w0, u1.x); fma2(acc[0][3], w0, u1.y);
            fma2(acc[1][0], w1, u0.x); fma2(acc[1][1], w1, u0.y);
            fma2(acc[1][2], w1, u1.x); fma2(acc[1][3], w1, u1.y);
        }
#pragma unroll
        for (int k = 0; k < 2; k++) {
            int oo = o + 64 * k;
            float bb = sm[L_CONST + 384 + oo];
            const float* X = sm + L_XP + (ln * 128 + oo) * 8;
            const float* fw = sm + L_CONST + 768 + oo * 8;
            float lsum = 0.f;
#pragma unroll
            for (int pr = 0; pr < 4; pr++) {
                float2 v = unpack2(acc[k][pr]);
                float v0 = fmaxf(X[2 * pr]     + v.x + bb, 0.f);
                float v1 = fmaxf(X[2 * pr + 1] + v.y + bb, 0.f);
                lsum += v0 * fw[2 * pr] + v1 * fw[2 * pr + 1];
            }
            sm[L_RED + ln * 128 + oo] = lsum;
        }
    }
    __syncthreads();

    // ---- reduce 128 partials per line ----
    if (tid < 128) {
        int ln = tid >> 5, lane = tid & 31;
        float s = sm[L_RED + ln * 128 + lane]
                + sm[L_RED + ln * 128 + lane + 32]
                + sm[L_RED + ln * 128 + lane + 64]
                + sm[L_RED + ln * 128 + lane + 96];
#pragma unroll
        for (int off = 16; off > 0; off >>= 1)
            s += __shfl_xor_sync(0xffffffffu, s, off);
        if (lane == 0) out[n0 + ln] = s + fc2b[0];
    }
}

// ---------------------------------------------------------------------------
extern "C" void kernel_launch(void* const* d_in, const int* in_sizes, int n_in,
                              void* d_out, int out_size) {
    const float* feature = (const float*)d_in[0];
    const float* lines   = (const float*)d_in[1];
    const float* fc1_w   = (const float*)d_in[2];
    const float* fc1_b   = (const float*)d_in[3];
    const float* bn1g = (const float*)d_in[4];
    const float* bn1b = (const float*)d_in[5];
    const float* bn1m = (const float*)d_in[6];
    const float* bn1v = (const float*)d_in[7];
    const float* c1w  = (const float*)d_in[8];
    const float* c1b  = (const float*)d_in[9];
    const float* bn2g = (const float*)d_in[10];
    const float* bn2b = (const float*)d_in[11];
    const float* bn2m = (const float*)d_in[12];
    const float* bn2v = (const float*)d_in[13];
    const float* c2w  = (const float*)d_in[14];
    const float* c2b  = (const float*)d_in[15];
    const float* bn3g = (const float*)d_in[16];
    const float* bn3b = (const float*)d_in[17];
    const float* bn3m = (const float*)d_in[18];
    const float* bn3v = (const float*)d_in[19];
    const float* c3w  = (const float*)d_in[20];
    const float* c3b  = (const float*)d_in[21];
    const float* fc2w = (const float*)d_in[22];
    const float* fc2b = (const float*)d_in[23];
    float* out = (float*)d_out;

    cudaFuncSetAttribute(k_fc1, cudaFuncAttributeMaxDynamicSharedMemorySize,
                         FC1_SMEM_BYTES);
    cudaFuncSetAttribute(k_lines, cudaFuncAttributeMaxDynamicSharedMemorySize,
                         K2_SMEM_BYTES);

    k_prep<<<64, 256>>>(fc1_w,
                        bn1g, bn1b, bn1m, bn1v, c1w, c1b,
                        bn2g, bn2b, bn2m, bn2v, c2w, c2b,
                        bn3g, bn3b, bn3m, bn3v, c3w, c3b, fc2w);

    dim3 g1(HW * HW / 128, NB);
    k_fc1<<<g1, 256, FC1_SMEM_BYTES>>>(feature, fc1_b);

    k_lines<<<NLINES / 4, 256, K2_SMEM_BYTES>>>(lines, fc2b, out);
}